// round 7
// baseline (speedup 1.0000x reference)
#include <cuda_runtime.h>
#include <math.h>

// Problem dims (fixed by the reference)
#define Bsz 256
#define Tsz 512
#define Isz 64
#define Hsz 512

// Partitioning: 16 batch-groups x 8 hout-groups = 128 CTAs per step
#define BG 16
#define JG 8
#define BT 16     // batch rows per CTA
#define JT 64     // output cols per CTA
#define NCTA (BG*JG)
#define NTHR 128

// Dynamic SMEM layout (float offsets)
#define WS_OFF   0                      // W_hh slice [512][64] = 32768 floats
#define WXS_OFF  (Hsz*JT)               // W_xh slice [64][64]  = 4096
#define HS_OFF   (WXS_OFF + Isz*JT)     // h stage    [512][16] = 8192
#define XS_OFF   (HS_OFF + Hsz*BT)      // x stage    [16][64]  = 1024
#define SMEM_FLOATS (XS_OFF + BT*Isz)
#define SMEM_BYTES  (SMEM_FLOATS * 4)   // 184,320 B -> 1 CTA/SM

// Double-buffered hidden state: [buf(2)][bg(16)][k(512)][b_in_group(16)]
// Step t reads buf (t&1), writes buf ((t+1)&1). Final h (t=511) lands in buf 0.
__device__ float g_h[2 * BG * Hsz * BT];

__device__ __forceinline__ void cp16(float* smem_dst, const float* gsrc) {
    unsigned d = (unsigned)__cvta_generic_to_shared(smem_dst);
    asm volatile("cp.async.cg.shared.global [%0], [%1], 16;" :: "r"(d), "l"(gsrc));
}
#define CP_COMMIT() asm volatile("cp.async.commit_group;")
#define CP_WAIT(n)  asm volatile("cp.async.wait_group %0;" :: "n"(n))

__global__ void __launch_bounds__(NTHR, 1)
rnn_step_kernel(const float* __restrict__ x,
                const float* __restrict__ Wxh,
                const float* __restrict__ Whh,
                const float* __restrict__ bias,
                int t)
{
    extern __shared__ float sm[];
    float* Ws  = sm + WS_OFF;
    float* Wxs = sm + WXS_OFF;
    float* hs  = sm + HS_OFF;
    float* xs  = sm + XS_OFF;

    const int tid  = threadIdx.x;
    const int bg   = blockIdx.x >> 3;   // 0..15
    const int jg   = blockIdx.x & 7;    // 0..7
    const int lane = tid & 31;
    const int wq   = tid >> 5;
    const int b0   = wq * 4;            // 4 batch rows per thread
    const int j0   = lane * 2;          // 2 output cols per thread

    const size_t xrow  = (size_t)Tsz * Isz;
    const float* xbase = x + (size_t)(bg * BT) * xrow + (size_t)t * Isz;

    // ---- Group A: x tile [16][64] + W_xh slice -> smem (async) ----
    #pragma unroll
    for (int m = 0; m < 2; ++m) {
        int idx = m * NTHR + tid;        // 0..255 float4
        int bb  = idx >> 4;
        int f   = idx & 15;
        cp16(xs + bb * Isz + f * 4, xbase + (size_t)bb * xrow + f * 4);
    }
    #pragma unroll
    for (int m = 0; m < 8; ++m) {
        int idx = m * NTHR + tid;        // 0..1023 float4
        int k   = idx >> 4;
        int f   = idx & 15;
        cp16(Wxs + k * JT + f * 4, Wxh + (size_t)k * Hsz + jg * JT + f * 4);
    }
    CP_COMMIT();

    // ---- Groups B,C (only when h exists): h stage, W_hh slice ----
    if (t > 0) {
        const float* hg = g_h + (size_t)((t & 1) * BG + bg) * (Hsz * BT);
        #pragma unroll
        for (int m = 0; m < 16; ++m) {
            int idx = m * NTHR + tid;    // 0..2047 float4 (linear copy)
            cp16(hs + idx * 4, hg + idx * 4);
        }
        CP_COMMIT();
        #pragma unroll 8
        for (int m = 0; m < 64; ++m) {
            int idx = m * NTHR + tid;    // 0..8191 float4
            int k   = idx >> 4;
            int f   = idx & 15;
            cp16(Ws + k * JT + f * 4, Whh + (size_t)k * Hsz + jg * JT + f * 4);
        }
        CP_COMMIT();
    }

    // acc init = bias (h_new = tanh(b + x W_xh + h W_hh))
    float bj0 = bias[jg * JT + j0];
    float bj1 = bias[jg * JT + j0 + 1];
    float acc[4][2];
    #pragma unroll
    for (int bi = 0; bi < 4; ++bi) { acc[bi][0] = bj0; acc[bi][1] = bj1; }

    // Wait for group A only (W_hh keeps streaming underneath the x-projection)
    if (t > 0) { CP_WAIT(2); } else { CP_WAIT(0); }
    __syncthreads();

    // ---- x-projection: acc += x[16,64] @ Wxh_slice[64,64] ----
    #pragma unroll 2
    for (int k = 0; k < Isz; k += 4) {
        float4 xv0 = *reinterpret_cast<const float4*>(xs + (b0 + 0) * Isz + k);
        float4 xv1 = *reinterpret_cast<const float4*>(xs + (b0 + 1) * Isz + k);
        float4 xv2 = *reinterpret_cast<const float4*>(xs + (b0 + 2) * Isz + k);
        float4 xv3 = *reinterpret_cast<const float4*>(xs + (b0 + 3) * Isz + k);
        #pragma unroll
        for (int u = 0; u < 4; ++u) {
            float2 w  = *reinterpret_cast<const float2*>(Wxs + (k + u) * JT + j0);
            float h0 = (&xv0.x)[u], h1 = (&xv1.x)[u], h2 = (&xv2.x)[u], h3 = (&xv3.x)[u];
            acc[0][0] += h0 * w.x; acc[0][1] += h0 * w.y;
            acc[1][0] += h1 * w.x; acc[1][1] += h1 * w.y;
            acc[2][0] += h2 * w.x; acc[2][1] += h2 * w.y;
            acc[3][0] += h3 * w.x; acc[3][1] += h3 * w.y;
        }
    }

    if (t > 0) {
        CP_WAIT(0);
        __syncthreads();
        // ---- Recurrent GEMM: acc += h[16,512] @ Whh_slice[512,64] ----
        #pragma unroll 4
        for (int k = 0; k < Hsz; ++k) {
            float4 hv = *reinterpret_cast<const float4*>(hs + k * BT + b0); // warp broadcast
            float2 w  = *reinterpret_cast<const float2*>(Ws + k * JT + j0);
            acc[0][0] += hv.x * w.x; acc[0][1] += hv.x * w.y;
            acc[1][0] += hv.y * w.x; acc[1][1] += hv.y * w.y;
            acc[2][0] += hv.z * w.x; acc[2][1] += hv.z * w.y;
            acc[3][0] += hv.w * w.x; acc[3][1] += hv.w * w.y;
        }
    }

    // ---- Epilogue: tanh + store h_new to write buffer ----
    float* hw = g_h + (size_t)((((t + 1) & 1)) * BG + bg) * (Hsz * BT);
    #pragma unroll
    for (int ji = 0; ji < 2; ++ji) {
        float4 o;
        o.x = tanhf(acc[0][ji]);
        o.y = tanhf(acc[1][ji]);
        o.z = tanhf(acc[2][ji]);
        o.w = tanhf(acc[3][ji]);
        *reinterpret_cast<float4*>(hw + (size_t)(jg * JT + j0 + ji) * BT + b0) = o;
    }
}

// out[b] = fc_b + sum_j fc_w[j] * h_final[b][j]; final h lives in buffer 0
__global__ void rnn_fc_kernel(const float* __restrict__ fcw,
                              const float* __restrict__ fcb,
                              float* __restrict__ out)
{
    int b    = blockIdx.x;       // 0..255
    int bg   = b >> 4;
    int bl   = b & 15;
    int lane = threadIdx.x;      // 32 threads

    const float* hg = g_h + (size_t)bg * (Hsz * BT);   // buffer 0
    float s = 0.f;
    #pragma unroll 4
    for (int j = lane; j < Hsz; j += 32)
        s += fcw[j] * hg[(size_t)j * BT + bl];
    #pragma unroll
    for (int o = 16; o; o >>= 1) s += __shfl_down_sync(0xffffffffu, s, o);
    if (lane == 0) out[b] = s + fcb[0];
}

extern "C" void kernel_launch(void* const* d_in, const int* in_sizes, int n_in,
                              void* d_out, int out_size)
{
    const float* x    = (const float*)d_in[0];   // (256, 512, 64)
    const float* Wxh  = (const float*)d_in[1];   // (64, 512)
    const float* Whh  = (const float*)d_in[2];   // (512, 512)
    const float* bias = (const float*)d_in[3];   // (512,)
    const float* fcw  = (const float*)d_in[4];   // (1, 512)
    const float* fcb  = (const float*)d_in[5];   // (1,)
    float* out = (float*)d_out;                  // (256, 1) fp32

    cudaFuncSetAttribute(rnn_step_kernel,
                         cudaFuncAttributeMaxDynamicSharedMemorySize, SMEM_BYTES);

    for (int t = 0; t < Tsz; ++t)
        rnn_step_kernel<<<NCTA, NTHR, SMEM_BYTES>>>(x, Wxh, Whh, bias, t);
    rnn_fc_kernel<<<Bsz, 32>>>(fcw, fcb, out);
}